// round 10
// baseline (speedup 1.0000x reference)
#include <cuda_runtime.h>
#include <cuda_fp16.h>
#include <cstdint>

// ---------------------------------------------------------------------------
// GCN_JK_Concat: 3x GCNConv(sym-norm, self-loops) + JK concat + Linear
// N=100000, E=1600000, F_IN=128, H=64, F_OUT=64
// R10: gather restructured -- 16 lanes/edge, 2 edges per warp feature LDG,
// chunk cv loaded once and shuffled (cuts warp-LDG count ~3x, instrs ~30%).
// Partial chunks use predicated-OFF loads (no request). scan_bsums folded
// into scan_add (one fewer launch). GEMMs on HMMA mma.sync (R7/R8).
// ---------------------------------------------------------------------------

#define NMAX   100000
#define EMAX   1600000
#define NNZMAX (EMAX + NMAX)
#define NBSCAN 128

__device__ int     g_deg[NMAX];               // starts 0; reset by scan
__device__ float   g_dis[NMAX];
__device__ int     g_rowptr[NMAX + 1];
__device__ int     g_cursor[NMAX];
__device__ int     g_bsum[NBSCAN];
__device__ int2    g_cv[NNZMAX];              // packed (col, val-bits)
__device__ __half2 g_hw[(size_t)NMAX * 32];   // fp16 transformed features
__device__ __half2 g_h1[(size_t)NMAX * 32];
__device__ __half2 g_h2[(size_t)NMAX * 32];
__device__ __half2 g_h3[(size_t)NMAX * 32];

// ===========================================================================
// CSR build
// ===========================================================================
__global__ void k_count2(const int* __restrict__ ei, int e) {
    int i = blockIdx.x * blockDim.x + threadIdx.x;
    int base = 2 * i;
    if (base + 1 < e) {
        int2 d = *(const int2*)&ei[(size_t)e + base];
        atomicAdd(&g_deg[d.x], 1);
        atomicAdd(&g_deg[d.y], 1);
    } else if (base < e) {
        atomicAdd(&g_deg[ei[(size_t)e + base]], 1);
    }
}

__global__ void __launch_bounds__(1024) k_scan_local(int n) {
    __shared__ int warpsum[32];
    int t = threadIdx.x;
    int lane = t & 31;
    int w = t >> 5;
    int i = blockIdx.x * 1024 + t;
    int v = 0;
    if (i < n) {
        v = g_deg[i] + 1;        // +1 = self-loop
        g_deg[i] = 0;            // reset for next graph replay
    }
    int s = v;
    #pragma unroll
    for (int o = 1; o < 32; o <<= 1) {
        int x = __shfl_up_sync(0xffffffffu, s, o);
        if (lane >= o) s += x;
    }
    if (lane == 31) warpsum[w] = s;
    __syncthreads();
    if (w == 0) {
        int v2 = warpsum[lane];
        #pragma unroll
        for (int o = 1; o < 32; o <<= 1) {
            int x = __shfl_up_sync(0xffffffffu, v2, o);
            if (lane >= o) v2 += x;
        }
        warpsum[lane] = v2;
    }
    __syncthreads();
    int prefix = (w == 0) ? 0 : warpsum[w - 1];
    int incl = prefix + s;
    if (i < n) {
        g_rowptr[i] = incl - v;
        g_dis[i] = rsqrtf((float)v);
    }
    if (t == 1023) g_bsum[blockIdx.x] = incl;
}

// Fused: per-block offset reduction + add pass (replaces scan_bsums+scan_add)
__global__ void __launch_bounds__(1024) k_scan_add(int nb, int n) {
    __shared__ int s_off;
    int t = threadIdx.x;
    int bid = blockIdx.x;
    if (t < 32) {
        int acc = 0;
        for (int j = t; j < nb; j += 32)
            if (j < bid) acc += g_bsum[j];
        #pragma unroll
        for (int o = 16; o; o >>= 1) acc += __shfl_down_sync(0xffffffffu, acc, o);
        if (t == 0) s_off = acc;
    }
    __syncthreads();
    int off = s_off;
    int i = bid * 1024 + t;
    if (i < n) {
        int rp = g_rowptr[i] + off;
        g_rowptr[i] = rp;
        g_cursor[i] = rp;
    }
    if (bid == gridDim.x - 1 && t < 32) {
        int acc2 = 0;
        for (int j = t; j < nb; j += 32) acc2 += g_bsum[j];
        #pragma unroll
        for (int o = 16; o; o >>= 1) acc2 += __shfl_down_sync(0xffffffffu, acc2, o);
        if (t == 0) g_rowptr[n] = acc2;
    }
}

__global__ void k_fill(const int* __restrict__ ei, int e, int n) {
    int i = blockIdx.x * blockDim.x + threadIdx.x;
    int s, d;
    if (i < e) {
        s = ei[i];
        d = ei[(size_t)e + i];
    } else if (i < e + n) {
        s = d = i - e;                  // self-loop
    } else {
        return;
    }
    int pos = atomicAdd(&g_cursor[d], 1);
    g_cv[pos] = make_int2(s, __float_as_int(g_dis[s] * g_dis[d]));
}

// ===========================================================================
// HMMA GEMM: out[n,64] = A[n,K] @ W[K,64]
// ===========================================================================
#define PADH 72

__device__ __forceinline__ uint32_t smem_u32(const void* p) {
    return (uint32_t)__cvta_generic_to_shared(p);
}

#define LDSM_X4(r0, r1, r2, r3, addr) \
    asm volatile("ldmatrix.sync.aligned.m8n8.x4.shared.b16 {%0,%1,%2,%3}, [%4];" \
        : "=r"(r0), "=r"(r1), "=r"(r2), "=r"(r3) : "r"(addr))

#define LDSM_X4_T(r0, r1, r2, r3, addr) \
    asm volatile("ldmatrix.sync.aligned.m8n8.x4.trans.shared.b16 {%0,%1,%2,%3}, [%4];" \
        : "=r"(r0), "=r"(r1), "=r"(r2), "=r"(r3) : "r"(addr))

#define MMA16816(d, a, b0, b1) \
    asm volatile("mma.sync.aligned.m16n8k16.row.col.f32.f16.f16.f32 " \
        "{%0,%1,%2,%3}, {%4,%5,%6,%7}, {%8,%9}, {%0,%1,%2,%3};" \
        : "+f"((d)[0]), "+f"((d)[1]), "+f"((d)[2]), "+f"((d)[3]) \
        : "r"((a)[0]), "r"((a)[1]), "r"((a)[2]), "r"((a)[3]), "r"(b0), "r"(b1))

struct HSmem {
    __half sA[128][PADH];
    __half sB[64][PADH];
};

__device__ __forceinline__ void load_A32(
    HSmem* sm, const float* __restrict__ A, int K, int kk,
    int rowBase, int n, int t)
{
    for (int idx = t; idx < 4096; idx += 128) {
        int row = idx >> 5, kp = idx & 31;
        int gr = rowBase + row;
        float2 f = make_float2(0.f, 0.f);
        if (gr < n) f = *(const float2*)&A[(size_t)gr * K + kk + 2 * kp];
        *(__half2*)&sm->sA[row][2 * kp] = __float22half2_rn(f);
    }
}

__device__ __forceinline__ void load_A16(
    HSmem* sm, const __half2* __restrict__ H, int rowBase, int n, int t)
{
    for (int idx = t; idx < 1024; idx += 128) {
        int row = idx >> 3, q = idx & 7;
        int gr = rowBase + row;
        uint4 v = make_uint4(0u, 0u, 0u, 0u);
        if (gr < n) v = *(const uint4*)&H[(size_t)gr * 32 + 4 * q];
        *(uint4*)&sm->sA[row][8 * q] = v;
    }
}

__device__ __forceinline__ void load_B(
    HSmem* sm, const float* __restrict__ W, int kk, int t)
{
    for (int idx = t; idx < 2048; idx += 128) {
        int k = idx >> 5, np = idx & 31;
        float2 f = *(const float2*)&W[(size_t)(kk + k) * 64 + 2 * np];
        *(__half2*)&sm->sB[k][2 * np] = __float22half2_rn(f);
    }
}

__device__ __forceinline__ void hmma_tile(
    HSmem* sm, int warp, int lane, float acc[2][8][4])
{
    #pragma unroll
    for (int kc = 0; kc < 4; kc++) {
        int k0 = kc * 16;
        uint32_t a[2][4];
        #pragma unroll
        for (int m = 0; m < 2; m++) {
            uint32_t addr = smem_u32(
                &sm->sA[warp * 32 + m * 16 + (lane & 15)][k0 + (lane >> 4) * 8]);
            LDSM_X4(a[m][0], a[m][1], a[m][2], a[m][3], addr);
        }
        #pragma unroll
        for (int jp = 0; jp < 4; jp++) {
            uint32_t b[4];
            uint32_t addr = smem_u32(
                &sm->sB[k0 + (lane & 15)][jp * 16 + (lane >> 4) * 8]);
            LDSM_X4_T(b[0], b[1], b[2], b[3], addr);
            #pragma unroll
            for (int m = 0; m < 2; m++) {
                MMA16816(acc[m][2 * jp],     a[m], b[0], b[1]);
                MMA16816(acc[m][2 * jp + 1], a[m], b[2], b[3]);
            }
        }
    }
}

__global__ void __launch_bounds__(128) k_hmma_xform(
    const float* __restrict__ A32,
    const __half2* __restrict__ A16,
    int K,
    const float* __restrict__ W,
    __half2* __restrict__ out, int n)
{
    __shared__ HSmem sm;
    int t = threadIdx.x;
    int lane = t & 31, warp = t >> 5;
    int rowBase = blockIdx.x * 128;
    float acc[2][8][4] = {};

    int nt = K >> 6;
    for (int i = 0; i < nt; i++) {
        if (A32) load_A32(&sm, A32, K, i * 64, rowBase, n, t);
        else     load_A16(&sm, A16 + (size_t)(i * 32), rowBase, n, t);
        load_B(&sm, W, i * 64, t);
        __syncthreads();
        hmma_tile(&sm, warp, lane, acc);
        __syncthreads();
    }

    int rw = rowBase + warp * 32;
    #pragma unroll
    for (int m = 0; m < 2; m++) {
        int r0 = rw + m * 16 + (lane >> 2);
        int r1 = r0 + 8;
        #pragma unroll
        for (int j = 0; j < 8; j++) {
            int col = 8 * j + 2 * (lane & 3);
            if (r0 < n)
                out[(size_t)r0 * 32 + (col >> 1)] =
                    __floats2half2_rn(acc[m][j][0], acc[m][j][1]);
            if (r1 < n)
                out[(size_t)r1 * 32 + (col >> 1)] =
                    __floats2half2_rn(acc[m][j][2], acc[m][j][3]);
        }
    }
}

__global__ void __launch_bounds__(128) k_hmma_cat(
    const float* __restrict__ x,
    const float* __restrict__ Wl,
    const float* __restrict__ bl,
    float* __restrict__ out, int n)
{
    __shared__ HSmem sm;
    int t = threadIdx.x;
    int lane = t & 31, warp = t >> 5;
    int rowBase = blockIdx.x * 128;
    float acc[2][8][4] = {};

    for (int i = 0; i < 5; i++) {
        if (i < 2)       load_A32(&sm, x, 128, i * 64, rowBase, n, t);
        else if (i == 2) load_A16(&sm, g_h1, rowBase, n, t);
        else if (i == 3) load_A16(&sm, g_h2, rowBase, n, t);
        else             load_A16(&sm, g_h3, rowBase, n, t);
        load_B(&sm, Wl, i * 64, t);
        __syncthreads();
        hmma_tile(&sm, warp, lane, acc);
        __syncthreads();
    }

    int rw = rowBase + warp * 32;
    #pragma unroll
    for (int m = 0; m < 2; m++) {
        int r0 = rw + m * 16 + (lane >> 2);
        int r1 = r0 + 8;
        #pragma unroll
        for (int j = 0; j < 8; j++) {
            int col = 8 * j + 2 * (lane & 3);
            float b0 = bl[col], b1 = bl[col + 1];
            if (r0 < n)
                *(float2*)&out[(size_t)r0 * 64 + col] =
                    make_float2(acc[m][j][0] + b0, acc[m][j][1] + b1);
            if (r1 < n)
                *(float2*)&out[(size_t)r1 * 64 + col] =
                    make_float2(acc[m][j][2] + b0, acc[m][j][3] + b1);
        }
    }
}

// ===========================================================================
// Aggregation v3: warp per node; 16 lanes per edge, 2 edges per feature LDG.
// Chunk of 8 edges: cv loaded once (8 lanes, 64B) and distributed via shfl;
// 4 feature warp-LDGs each covering 2 edges (two 128B lines). OOB edges are
// predicated OFF (no memory request). Halves combined with shfl_xor(16).
// ===========================================================================
__global__ void __launch_bounds__(256) k_gather(
    const __half2* __restrict__ hw,
    const float* __restrict__ bias,
    __half2* __restrict__ hout, int n)
{
    int g = blockIdx.x * blockDim.x + threadIdx.x;
    int node = g >> 5;
    int lane = g & 31;
    if (node >= n) return;
    int beg = g_rowptr[node];
    int end = g_rowptr[node + 1];
    int half = lane >> 4;      // which edge of the pair
    int sub  = lane & 15;      // 4-col slice of the feature row
    float a0 = 0.f, a1 = 0.f, a2 = 0.f, a3 = 0.f;

    for (int e = beg; e < end; e += 8) {
        int idx = e + (lane & 7);
        int2 cv = make_int2(0, 0);
        if (idx < end) cv = __ldg(&g_cv[idx]);
        #pragma unroll
        for (int s = 0; s < 4; s++) {
            int src = 2 * s + half;                 // edge slot 0..7
            int col  = __shfl_sync(0xffffffffu, cv.x, src);
            float v  = __int_as_float(__shfl_sync(0xffffffffu, cv.y, src));
            float2 f01 = make_float2(0.f, 0.f), f23 = make_float2(0.f, 0.f);
            if (e + src < end) {                    // predicated-off when OOB
                uint2 q = __ldg((const uint2*)(hw + (size_t)col * 32 + 2 * sub));
                f01 = __half22float2(*(__half2*)&q.x);
                f23 = __half22float2(*(__half2*)&q.y);
            }
            a0 = fmaf(v, f01.x, a0); a1 = fmaf(v, f01.y, a1);
            a2 = fmaf(v, f23.x, a2); a3 = fmaf(v, f23.y, a3);
        }
    }
    // combine the two edge-halves (same 4 columns)
    a0 += __shfl_xor_sync(0xffffffffu, a0, 16);
    a1 += __shfl_xor_sync(0xffffffffu, a1, 16);
    a2 += __shfl_xor_sync(0xffffffffu, a2, 16);
    a3 += __shfl_xor_sync(0xffffffffu, a3, 16);

    if (half == 0) {
        float4 bv = *(const float4*)&bias[4 * sub];
        __half2 o0 = __floats2half2_rn(fmaxf(a0 + bv.x, 0.f), fmaxf(a1 + bv.y, 0.f));
        __half2 o1 = __floats2half2_rn(fmaxf(a2 + bv.z, 0.f), fmaxf(a3 + bv.w, 0.f));
        uint2 q;
        q.x = *(uint32_t*)&o0;
        q.y = *(uint32_t*)&o1;
        *(uint2*)(hout + (size_t)node * 32 + 2 * sub) = q;
    }
}

// ---------------------------------------------------------------------------
extern "C" void kernel_launch(void* const* d_in, const int* in_sizes, int n_in,
                              void* d_out, int out_size)
{
    const float* x  = (const float*)d_in[0];
    const int*   ei = (const int*)d_in[1];     // int32 edge_index [2, E]
    const float* W0 = (const float*)d_in[2];
    const float* b0 = (const float*)d_in[3];
    const float* W1 = (const float*)d_in[4];
    const float* b1 = (const float*)d_in[5];
    const float* W2 = (const float*)d_in[6];
    const float* b2 = (const float*)d_in[7];
    const float* Wl = (const float*)d_in[8];
    const float* bl = (const float*)d_in[9];
    float* out = (float*)d_out;

    int n = in_sizes[0] / 128;
    int e = in_sizes[1] / 2;
    int nb = (n + 1023) >> 10;

    __half2 *hw_ptr = nullptr, *h1_ptr = nullptr, *h2_ptr = nullptr, *h3_ptr = nullptr;
    cudaGetSymbolAddress((void**)&hw_ptr, g_hw);
    cudaGetSymbolAddress((void**)&h1_ptr, g_h1);
    cudaGetSymbolAddress((void**)&h2_ptr, g_h2);
    cudaGetSymbolAddress((void**)&h3_ptr, g_h3);

    // ---- CSR build ----
    int cth = (e + 1) / 2;
    k_count2<<<(cth + 255) / 256, 256>>>(ei, e);
    k_scan_local<<<nb, 1024>>>(n);
    k_scan_add<<<nb, 1024>>>(nb, n);
    k_fill<<<(e + n + 255) / 256, 256>>>(ei, e, n);

    int mma_blocks = (n + 127) / 128;
    int gather_blocks = (n * 32 + 255) / 256;

    // ---- layer 1 ----
    k_hmma_xform<<<mma_blocks, 128>>>(x, nullptr, 128, W0, hw_ptr, n);
    k_gather<<<gather_blocks, 256>>>(hw_ptr, b0, h1_ptr, n);
    // ---- layer 2 ----
    k_hmma_xform<<<mma_blocks, 128>>>(nullptr, h1_ptr, 64, W1, hw_ptr, n);
    k_gather<<<gather_blocks, 256>>>(hw_ptr, b1, h2_ptr, n);
    // ---- layer 3 ----
    k_hmma_xform<<<mma_blocks, 128>>>(nullptr, h2_ptr, 64, W2, hw_ptr, n);
    k_gather<<<gather_blocks, 256>>>(hw_ptr, b2, h3_ptr, n);
    // ---- JK concat + linear ----
    k_hmma_cat<<<mma_blocks, 128>>>(x, Wl, bl, out, n);
}

// round 11
// speedup vs baseline: 1.1199x; 1.1199x over previous
#include <cuda_runtime.h>
#include <cuda_fp16.h>
#include <cstdint>

// ---------------------------------------------------------------------------
// GCN_JK_Concat: 3x GCNConv(sym-norm, self-loops) + JK concat + Linear
// N=100000, E=1600000, F_IN=128, H=64, F_OUT=64
// R11: R8 gather (proven best) + fused scan_add (R10) + layer-1 GEMM also
// produces partial = x @ Wl[0:128] so the concat GEMM never re-reads x
// (removes a 51MB DRAM stream). HMMA GEMMs throughout.
// ---------------------------------------------------------------------------

#define NMAX   100000
#define EMAX   1600000
#define NNZMAX (EMAX + NMAX)
#define NBSCAN 128

__device__ int     g_deg[NMAX];               // starts 0; reset by scan
__device__ float   g_dis[NMAX];
__device__ int     g_rowptr[NMAX + 1];
__device__ int     g_cursor[NMAX];
__device__ int     g_bsum[NBSCAN];
__device__ int2    g_cv[NNZMAX];              // packed (col, val-bits)
__device__ __half2 g_hw[(size_t)NMAX * 32];   // fp16 transformed features
__device__ __half2 g_h1[(size_t)NMAX * 32];
__device__ __half2 g_h2[(size_t)NMAX * 32];
__device__ __half2 g_h3[(size_t)NMAX * 32];
__device__ float   g_part[(size_t)NMAX * 64]; // x @ Wl[0:128] partial (fp32)

// ===========================================================================
// CSR build
// ===========================================================================
__global__ void k_count2(const int* __restrict__ ei, int e) {
    int i = blockIdx.x * blockDim.x + threadIdx.x;
    int base = 2 * i;
    if (base + 1 < e) {
        int2 d = *(const int2*)&ei[(size_t)e + base];
        atomicAdd(&g_deg[d.x], 1);
        atomicAdd(&g_deg[d.y], 1);
    } else if (base < e) {
        atomicAdd(&g_deg[ei[(size_t)e + base]], 1);
    }
}

__global__ void __launch_bounds__(1024) k_scan_local(int n) {
    __shared__ int warpsum[32];
    int t = threadIdx.x;
    int lane = t & 31;
    int w = t >> 5;
    int i = blockIdx.x * 1024 + t;
    int v = 0;
    if (i < n) {
        v = g_deg[i] + 1;        // +1 = self-loop
        g_deg[i] = 0;            // reset for next graph replay
    }
    int s = v;
    #pragma unroll
    for (int o = 1; o < 32; o <<= 1) {
        int x = __shfl_up_sync(0xffffffffu, s, o);
        if (lane >= o) s += x;
    }
    if (lane == 31) warpsum[w] = s;
    __syncthreads();
    if (w == 0) {
        int v2 = warpsum[lane];
        #pragma unroll
        for (int o = 1; o < 32; o <<= 1) {
            int x = __shfl_up_sync(0xffffffffu, v2, o);
            if (lane >= o) v2 += x;
        }
        warpsum[lane] = v2;
    }
    __syncthreads();
    int prefix = (w == 0) ? 0 : warpsum[w - 1];
    int incl = prefix + s;
    if (i < n) {
        g_rowptr[i] = incl - v;
        g_dis[i] = rsqrtf((float)v);
    }
    if (t == 1023) g_bsum[blockIdx.x] = incl;
}

// Fused: per-block offset reduction + add pass
__global__ void __launch_bounds__(1024) k_scan_add(int nb, int n) {
    __shared__ int s_off;
    int t = threadIdx.x;
    int bid = blockIdx.x;
    if (t < 32) {
        int acc = 0;
        for (int j = t; j < nb; j += 32)
            if (j < bid) acc += g_bsum[j];
        #pragma unroll
        for (int o = 16; o; o >>= 1) acc += __shfl_down_sync(0xffffffffu, acc, o);
        if (t == 0) s_off = acc;
    }
    __syncthreads();
    int off = s_off;
    int i = bid * 1024 + t;
    if (i < n) {
        int rp = g_rowptr[i] + off;
        g_rowptr[i] = rp;
        g_cursor[i] = rp;
    }
    if (bid == gridDim.x - 1 && t < 32) {
        int acc2 = 0;
        for (int j = t; j < nb; j += 32) acc2 += g_bsum[j];
        #pragma unroll
        for (int o = 16; o; o >>= 1) acc2 += __shfl_down_sync(0xffffffffu, acc2, o);
        if (t == 0) g_rowptr[n] = acc2;
    }
}

__global__ void k_fill(const int* __restrict__ ei, int e, int n) {
    int i = blockIdx.x * blockDim.x + threadIdx.x;
    int s, d;
    if (i < e) {
        s = ei[i];
        d = ei[(size_t)e + i];
    } else if (i < e + n) {
        s = d = i - e;                  // self-loop
    } else {
        return;
    }
    int pos = atomicAdd(&g_cursor[d], 1);
    g_cv[pos] = make_int2(s, __float_as_int(g_dis[s] * g_dis[d]));
}

// ===========================================================================
// HMMA GEMM machinery
// ===========================================================================
#define PADH 72

__device__ __forceinline__ uint32_t smem_u32(const void* p) {
    return (uint32_t)__cvta_generic_to_shared(p);
}

#define LDSM_X4(r0, r1, r2, r3, addr) \
    asm volatile("ldmatrix.sync.aligned.m8n8.x4.shared.b16 {%0,%1,%2,%3}, [%4];" \
        : "=r"(r0), "=r"(r1), "=r"(r2), "=r"(r3) : "r"(addr))

#define LDSM_X4_T(r0, r1, r2, r3, addr) \
    asm volatile("ldmatrix.sync.aligned.m8n8.x4.trans.shared.b16 {%0,%1,%2,%3}, [%4];" \
        : "=r"(r0), "=r"(r1), "=r"(r2), "=r"(r3) : "r"(addr))

#define MMA16816(d, a, b0, b1) \
    asm volatile("mma.sync.aligned.m16n8k16.row.col.f32.f16.f16.f32 " \
        "{%0,%1,%2,%3}, {%4,%5,%6,%7}, {%8,%9}, {%0,%1,%2,%3};" \
        : "+f"((d)[0]), "+f"((d)[1]), "+f"((d)[2]), "+f"((d)[3]) \
        : "r"((a)[0]), "r"((a)[1]), "r"((a)[2]), "r"((a)[3]), "r"(b0), "r"(b1))

typedef __half ARow[PADH];

__device__ __forceinline__ void load_A32g(
    ARow* sA, const float* __restrict__ A, int K, int kk,
    int rowBase, int n, int t)
{
    for (int idx = t; idx < 4096; idx += 128) {
        int row = idx >> 5, kp = idx & 31;
        int gr = rowBase + row;
        float2 f = make_float2(0.f, 0.f);
        if (gr < n) f = *(const float2*)&A[(size_t)gr * K + kk + 2 * kp];
        *(__half2*)&sA[row][2 * kp] = __float22half2_rn(f);
    }
}

__device__ __forceinline__ void load_A16g(
    ARow* sA, const __half2* __restrict__ H, int rowBase, int n, int t)
{
    for (int idx = t; idx < 1024; idx += 128) {
        int row = idx >> 3, q = idx & 7;
        int gr = rowBase + row;
        uint4 v = make_uint4(0u, 0u, 0u, 0u);
        if (gr < n) v = *(const uint4*)&H[(size_t)gr * 32 + 4 * q];
        *(uint4*)&sA[row][8 * q] = v;
    }
}

__device__ __forceinline__ void load_Bg(
    ARow* sB, const float* __restrict__ W, int kk, int t)
{
    for (int idx = t; idx < 2048; idx += 128) {
        int k = idx >> 5, np = idx & 31;
        float2 f = *(const float2*)&W[(size_t)(kk + k) * 64 + 2 * np];
        *(__half2*)&sB[k][2 * np] = __float22half2_rn(f);
    }
}

__device__ __forceinline__ void hmma_tile_g(
    ARow* sA, ARow* sB, int warp, int lane, float acc[2][8][4])
{
    #pragma unroll
    for (int kc = 0; kc < 4; kc++) {
        int k0 = kc * 16;
        uint32_t a[2][4];
        #pragma unroll
        for (int m = 0; m < 2; m++) {
            uint32_t addr = smem_u32(
                &sA[warp * 32 + m * 16 + (lane & 15)][k0 + (lane >> 4) * 8]);
            LDSM_X4(a[m][0], a[m][1], a[m][2], a[m][3], addr);
        }
        #pragma unroll
        for (int jp = 0; jp < 4; jp++) {
            uint32_t b[4];
            uint32_t addr = smem_u32(
                &sB[k0 + (lane & 15)][jp * 16 + (lane >> 4) * 8]);
            LDSM_X4_T(b[0], b[1], b[2], b[3], addr);
            #pragma unroll
            for (int m = 0; m < 2; m++) {
                MMA16816(acc[m][2 * jp],     a[m], b[0], b[1]);
                MMA16816(acc[m][2 * jp + 1], a[m], b[2], b[3]);
            }
        }
    }
}

// ---------------------------------------------------------------------------
// Layer-1 fused GEMM: hw = fp16(x@W0)  AND  g_part = fp32(x@Wl[0:128])
// ---------------------------------------------------------------------------
__global__ void __launch_bounds__(128) k_hmma_l1(
    const float* __restrict__ x,
    const float* __restrict__ W0,
    const float* __restrict__ Wl,
    __half2* __restrict__ out, int n)
{
    __shared__ __half sA[128][PADH];
    __shared__ __half sBw[64][PADH];
    __shared__ __half sBl[64][PADH];
    int t = threadIdx.x;
    int lane = t & 31, warp = t >> 5;
    int rowBase = blockIdx.x * 128;
    float accW[2][8][4] = {};
    float accL[2][8][4] = {};

    for (int i = 0; i < 2; i++) {
        load_A32g(sA, x, 128, i * 64, rowBase, n, t);
        load_Bg(sBw, W0, i * 64, t);
        load_Bg(sBl, Wl, i * 64, t);
        __syncthreads();
        hmma_tile_g(sA, sBw, warp, lane, accW);
        hmma_tile_g(sA, sBl, warp, lane, accL);
        __syncthreads();
    }

    int rw = rowBase + warp * 32;
    #pragma unroll
    for (int m = 0; m < 2; m++) {
        int r0 = rw + m * 16 + (lane >> 2);
        int r1 = r0 + 8;
        #pragma unroll
        for (int j = 0; j < 8; j++) {
            int col = 8 * j + 2 * (lane & 3);
            if (r0 < n) {
                out[(size_t)r0 * 32 + (col >> 1)] =
                    __floats2half2_rn(accW[m][j][0], accW[m][j][1]);
                *(float2*)&g_part[(size_t)r0 * 64 + col] =
                    make_float2(accL[m][j][0], accL[m][j][1]);
            }
            if (r1 < n) {
                out[(size_t)r1 * 32 + (col >> 1)] =
                    __floats2half2_rn(accW[m][j][2], accW[m][j][3]);
                *(float2*)&g_part[(size_t)r1 * 64 + col] =
                    make_float2(accL[m][j][2], accL[m][j][3]);
            }
        }
    }
}

// Layers 2,3 transform GEMM: out = fp16(A16 @ W), K=64
__global__ void __launch_bounds__(128) k_hmma_xform(
    const __half2* __restrict__ A16,
    const float* __restrict__ W,
    __half2* __restrict__ out, int n)
{
    __shared__ __half sA[128][PADH];
    __shared__ __half sB[64][PADH];
    int t = threadIdx.x;
    int lane = t & 31, warp = t >> 5;
    int rowBase = blockIdx.x * 128;
    float acc[2][8][4] = {};

    load_A16g(sA, A16, rowBase, n, t);
    load_Bg(sB, W, 0, t);
    __syncthreads();
    hmma_tile_g(sA, sB, warp, lane, acc);
    __syncthreads();

    int rw = rowBase + warp * 32;
    #pragma unroll
    for (int m = 0; m < 2; m++) {
        int r0 = rw + m * 16 + (lane >> 2);
        int r1 = r0 + 8;
        #pragma unroll
        for (int j = 0; j < 8; j++) {
            int col = 8 * j + 2 * (lane & 3);
            if (r0 < n)
                out[(size_t)r0 * 32 + (col >> 1)] =
                    __floats2half2_rn(acc[m][j][0], acc[m][j][1]);
            if (r1 < n)
                out[(size_t)r1 * 32 + (col >> 1)] =
                    __floats2half2_rn(acc[m][j][2], acc[m][j][3]);
        }
    }
}

// Final GEMM: out = partial + [h1|h2|h3] @ Wl[128:320] + bl   (K=192, fp16 A)
__global__ void __launch_bounds__(128) k_hmma_cat(
    const float* __restrict__ Wl,
    const float* __restrict__ bl,
    float* __restrict__ out, int n)
{
    __shared__ __half sA[128][PADH];
    __shared__ __half sB[64][PADH];
    int t = threadIdx.x;
    int lane = t & 31, warp = t >> 5;
    int rowBase = blockIdx.x * 128;
    float acc[2][8][4] = {};
    const float* Wl2 = Wl + 128 * 64;

    for (int i = 0; i < 3; i++) {
        const __half2* src = (i == 0) ? g_h1 : (i == 1) ? g_h2 : g_h3;
        load_A16g(sA, src, rowBase, n, t);
        load_Bg(sB, Wl2, i * 64, t);
        __syncthreads();
        hmma_tile_g(sA, sB, warp, lane, acc);
        __syncthreads();
    }

    int rw = rowBase + warp * 32;
    #pragma unroll
    for (int m = 0; m < 2; m++) {
        int r0 = rw + m * 16 + (lane >> 2);
        int r1 = r0 + 8;
        #pragma unroll
        for (int j = 0; j < 8; j++) {
            int col = 8 * j + 2 * (lane & 3);
            float b0 = bl[col], b1 = bl[col + 1];
            if (r0 < n) {
                float2 p = *(const float2*)&g_part[(size_t)r0 * 64 + col];
                *(float2*)&out[(size_t)r0 * 64 + col] =
                    make_float2(acc[m][j][0] + p.x + b0, acc[m][j][1] + p.y + b1);
            }
            if (r1 < n) {
                float2 p = *(const float2*)&g_part[(size_t)r1 * 64 + col];
                *(float2*)&out[(size_t)r1 * 64 + col] =
                    make_float2(acc[m][j][2] + p.x + b0, acc[m][j][3] + p.y + b1);
            }
        }
    }
}

// ===========================================================================
// Aggregation (R8 exact): warp per node, lane = one half2 (2 cols), unroll x8
// with all cv loads issued before feature loads.
// ===========================================================================
__global__ void __launch_bounds__(256) k_gather(
    const __half2* __restrict__ hw,
    const float* __restrict__ bias,
    __half2* __restrict__ hout, int n)
{
    int g = blockIdx.x * blockDim.x + threadIdx.x;
    int node = g >> 5;
    int lane = g & 31;
    if (node >= n) return;
    int beg = g_rowptr[node];
    int end = g_rowptr[node + 1];
    float a0 = 0.f, a1 = 0.f;
    int e = beg;
    for (; e + 7 < end; e += 8) {
        int2 cv[8];
        #pragma unroll
        for (int j = 0; j < 8; j++) cv[j] = __ldg(&g_cv[e + j]);
        float2 f[8];
        #pragma unroll
        for (int j = 0; j < 8; j++)
            f[j] = __half22float2(hw[(size_t)cv[j].x * 32 + lane]);
        #pragma unroll
        for (int j = 0; j < 8; j++) {
            float v = __int_as_float(cv[j].y);
            a0 = fmaf(v, f[j].x, a0);
            a1 = fmaf(v, f[j].y, a1);
        }
    }
    for (; e < end; e++) {
        int2 cv = __ldg(&g_cv[e]);
        float2 f = __half22float2(hw[(size_t)cv.x * 32 + lane]);
        float v = __int_as_float(cv.y);
        a0 = fmaf(v, f.x, a0); a1 = fmaf(v, f.y, a1);
    }
    float b0 = bias[2 * lane], b1 = bias[2 * lane + 1];
    hout[(size_t)node * 32 + lane] =
        __floats2half2_rn(fmaxf(a0 + b0, 0.f), fmaxf(a1 + b1, 0.f));
}

// ---------------------------------------------------------------------------
extern "C" void kernel_launch(void* const* d_in, const int* in_sizes, int n_in,
                              void* d_out, int out_size)
{
    const float* x  = (const float*)d_in[0];
    const int*   ei = (const int*)d_in[1];     // int32 edge_index [2, E]
    const float* W0 = (const float*)d_in[2];
    const float* b0 = (const float*)d_in[3];
    const float* W1 = (const float*)d_in[4];
    const float* b1 = (const float*)d_in[5];
    const float* W2 = (const float*)d_in[6];
    const float* b2 = (const float*)d_in[7];
    const float* Wl = (const float*)d_in[8];
    const float* bl = (const float*)d_in[9];
    float* out = (float*)d_out;

    int n = in_sizes[0] / 128;
    int e = in_sizes[1] / 2;
    int nb = (n + 1023) >> 10;

    __half2 *hw_ptr = nullptr, *h1_ptr = nullptr, *h2_ptr = nullptr, *h3_ptr = nullptr;
    cudaGetSymbolAddress((void**)&hw_ptr, g_hw);
    cudaGetSymbolAddress((void**)&h1_ptr, g_h1);
    cudaGetSymbolAddress((void**)&h2_ptr, g_h2);
    cudaGetSymbolAddress((void**)&h3_ptr, g_h3);

    // ---- CSR build ----
    int cth = (e + 1) / 2;
    k_count2<<<(cth + 255) / 256, 256>>>(ei, e);
    k_scan_local<<<nb, 1024>>>(n);
    k_scan_add<<<nb, 1024>>>(nb, n);
    k_fill<<<(e + n + 255) / 256, 256>>>(ei, e, n);

    int mma_blocks = (n + 127) / 128;
    int gather_blocks = (n * 32 + 255) / 256;

    // ---- layer 1 (+ partial for final linear) ----
    k_hmma_l1<<<mma_blocks, 128>>>(x, W0, Wl, hw_ptr, n);
    k_gather<<<gather_blocks, 256>>>(hw_ptr, b0, h1_ptr, n);
    // ---- layer 2 ----
    k_hmma_xform<<<mma_blocks, 128>>>(h1_ptr, W1, hw_ptr, n);
    k_gather<<<gather_blocks, 256>>>(hw_ptr, b1, h2_ptr, n);
    // ---- layer 3 ----
    k_hmma_xform<<<mma_blocks, 128>>>(h2_ptr, W2, hw_ptr, n);
    k_gather<<<gather_blocks, 256>>>(hw_ptr, b2, h3_ptr, n);
    // ---- JK concat + linear (K=192 fp16 + partial) ----
    k_hmma_cat<<<mma_blocks, 128>>>(Wl, bl, out, n);
}

// round 12
// speedup vs baseline: 1.1341x; 1.0127x over previous
#include <cuda_runtime.h>
#include <cuda_fp16.h>
#include <cstdint>

// ---------------------------------------------------------------------------
// GCN_JK_Concat: 3x GCNConv(sym-norm, self-loops) + JK concat + Linear
// N=100000, E=1600000, F_IN=128, H=64, F_OUT=64
// R12: R11 base + (1) gather cv loads as uniform int4 (half the LDG issues on
// the saturated LSU/MIO pipe), (2) layer-1 GEMM overlapped with CSR build on
// a second stream (event fork/join, capture-legal), (3) int4 k_count.
// ---------------------------------------------------------------------------

#define NMAX   100000
#define EMAX   1600000
#define NNZMAX (EMAX + NMAX)
#define NBSCAN 128

__device__ int     g_deg[NMAX];               // starts 0; reset by scan
__device__ float   g_dis[NMAX];
__device__ int     g_rowptr[NMAX + 1];
__device__ int     g_cursor[NMAX];
__device__ int     g_bsum[NBSCAN];
__device__ int2    g_cv[NNZMAX];              // packed (col, val-bits)
__device__ __half2 g_hw[(size_t)NMAX * 32];   // fp16 transformed features
__device__ __half2 g_h1[(size_t)NMAX * 32];
__device__ __half2 g_h2[(size_t)NMAX * 32];
__device__ __half2 g_h3[(size_t)NMAX * 32];
__device__ float   g_part[(size_t)NMAX * 64]; // x @ Wl[0:128] partial (fp32)

// ===========================================================================
// CSR build
// ===========================================================================
__global__ void k_count4(const int* __restrict__ ei, int e) {
    int i = blockIdx.x * blockDim.x + threadIdx.x;
    int base = 4 * i;
    if (base + 3 < e) {
        int4 d = *(const int4*)&ei[(size_t)e + base];
        atomicAdd(&g_deg[d.x], 1);
        atomicAdd(&g_deg[d.y], 1);
        atomicAdd(&g_deg[d.z], 1);
        atomicAdd(&g_deg[d.w], 1);
    } else {
        for (int j = base; j < e; j++)
            atomicAdd(&g_deg[ei[(size_t)e + j]], 1);
    }
}

__global__ void k_count1(const int* __restrict__ ei, int e) {
    int i = blockIdx.x * blockDim.x + threadIdx.x;
    if (i < e) atomicAdd(&g_deg[ei[(size_t)e + i]], 1);
}

__global__ void __launch_bounds__(1024) k_scan_local(int n) {
    __shared__ int warpsum[32];
    int t = threadIdx.x;
    int lane = t & 31;
    int w = t >> 5;
    int i = blockIdx.x * 1024 + t;
    int v = 0;
    if (i < n) {
        v = g_deg[i] + 1;        // +1 = self-loop
        g_deg[i] = 0;            // reset for next graph replay
    }
    int s = v;
    #pragma unroll
    for (int o = 1; o < 32; o <<= 1) {
        int x = __shfl_up_sync(0xffffffffu, s, o);
        if (lane >= o) s += x;
    }
    if (lane == 31) warpsum[w] = s;
    __syncthreads();
    if (w == 0) {
        int v2 = warpsum[lane];
        #pragma unroll
        for (int o = 1; o < 32; o <<= 1) {
            int x = __shfl_up_sync(0xffffffffu, v2, o);
            if (lane >= o) v2 += x;
        }
        warpsum[lane] = v2;
    }
    __syncthreads();
    int prefix = (w == 0) ? 0 : warpsum[w - 1];
    int incl = prefix + s;
    if (i < n) {
        g_rowptr[i] = incl - v;
        g_dis[i] = rsqrtf((float)v);
    }
    if (t == 1023) g_bsum[blockIdx.x] = incl;
}

// Fused: per-block offset reduction + add pass
__global__ void __launch_bounds__(1024) k_scan_add(int nb, int n) {
    __shared__ int s_off;
    int t = threadIdx.x;
    int bid = blockIdx.x;
    if (t < 32) {
        int acc = 0;
        for (int j = t; j < nb; j += 32)
            if (j < bid) acc += g_bsum[j];
        #pragma unroll
        for (int o = 16; o; o >>= 1) acc += __shfl_down_sync(0xffffffffu, acc, o);
        if (t == 0) s_off = acc;
    }
    __syncthreads();
    int off = s_off;
    int i = bid * 1024 + t;
    if (i < n) {
        int rp = g_rowptr[i] + off;
        g_rowptr[i] = rp;
        g_cursor[i] = rp;
    }
    if (bid == gridDim.x - 1 && t < 32) {
        int acc2 = 0;
        for (int j = t; j < nb; j += 32) acc2 += g_bsum[j];
        #pragma unroll
        for (int o = 16; o; o >>= 1) acc2 += __shfl_down_sync(0xffffffffu, acc2, o);
        if (t == 0) g_rowptr[n] = acc2;
    }
}

__global__ void k_fill(const int* __restrict__ ei, int e, int n) {
    int i = blockIdx.x * blockDim.x + threadIdx.x;
    int s, d;
    if (i < e) {
        s = ei[i];
        d = ei[(size_t)e + i];
    } else if (i < e + n) {
        s = d = i - e;                  // self-loop
    } else {
        return;
    }
    int pos = atomicAdd(&g_cursor[d], 1);
    g_cv[pos] = make_int2(s, __float_as_int(g_dis[s] * g_dis[d]));
}

// ===========================================================================
// HMMA GEMM machinery
// ===========================================================================
#define PADH 72

__device__ __forceinline__ uint32_t smem_u32(const void* p) {
    return (uint32_t)__cvta_generic_to_shared(p);
}

#define LDSM_X4(r0, r1, r2, r3, addr) \
    asm volatile("ldmatrix.sync.aligned.m8n8.x4.shared.b16 {%0,%1,%2,%3}, [%4];" \
        : "=r"(r0), "=r"(r1), "=r"(r2), "=r"(r3) : "r"(addr))

#define LDSM_X4_T(r0, r1, r2, r3, addr) \
    asm volatile("ldmatrix.sync.aligned.m8n8.x4.trans.shared.b16 {%0,%1,%2,%3}, [%4];" \
        : "=r"(r0), "=r"(r1), "=r"(r2), "=r"(r3) : "r"(addr))

#define MMA16816(d, a, b0, b1) \
    asm volatile("mma.sync.aligned.m16n8k16.row.col.f32.f16.f16.f32 " \
        "{%0,%1,%2,%3}, {%4,%5,%6,%7}, {%8,%9}, {%0,%1,%2,%3};" \
        : "+f"((d)[0]), "+f"((d)[1]), "+f"((d)[2]), "+f"((d)[3]) \
        : "r"((a)[0]), "r"((a)[1]), "r"((a)[2]), "r"((a)[3]), "r"(b0), "r"(b1))

typedef __half ARow[PADH];

__device__ __forceinline__ void load_A32g(
    ARow* sA, const float* __restrict__ A, int K, int kk,
    int rowBase, int n, int t)
{
    for (int idx = t; idx < 4096; idx += 128) {
        int row = idx >> 5, kp = idx & 31;
        int gr = rowBase + row;
        float2 f = make_float2(0.f, 0.f);
        if (gr < n) f = *(const float2*)&A[(size_t)gr * K + kk + 2 * kp];
        *(__half2*)&sA[row][2 * kp] = __float22half2_rn(f);
    }
}

__device__ __forceinline__ void load_A16g(
    ARow* sA, const __half2* __restrict__ H, int rowBase, int n, int t)
{
    for (int idx = t; idx < 1024; idx += 128) {
        int row = idx >> 3, q = idx & 7;
        int gr = rowBase + row;
        uint4 v = make_uint4(0u, 0u, 0u, 0u);
        if (gr < n) v = *(const uint4*)&H[(size_t)gr * 32 + 4 * q];
        *(uint4*)&sA[row][8 * q] = v;
    }
}

__device__ __forceinline__ void load_Bg(
    ARow* sB, const float* __restrict__ W, int kk, int t)
{
    for (int idx = t; idx < 2048; idx += 128) {
        int k = idx >> 5, np = idx & 31;
        float2 f = *(const float2*)&W[(size_t)(kk + k) * 64 + 2 * np];
        *(__half2*)&sB[k][2 * np] = __float22half2_rn(f);
    }
}

__device__ __forceinline__ void hmma_tile_g(
    ARow* sA, ARow* sB, int warp, int lane, float acc[2][8][4])
{
    #pragma unroll
    for (int kc = 0; kc < 4; kc++) {
        int k0 = kc * 16;
        uint32_t a[2][4];
        #pragma unroll
        for (int m = 0; m < 2; m++) {
            uint32_t addr = smem_u32(
                &sA[warp * 32 + m * 16 + (lane & 15)][k0 + (lane >> 4) * 8]);
            LDSM_X4(a[m][0], a[m][1], a[m][2], a[m][3], addr);
        }
        #pragma unroll
        for (int jp = 0; jp < 4; jp++) {
            uint32_t b[4];
            uint32_t addr = smem_u32(
                &sB[k0 + (lane & 15)][jp * 16 + (lane >> 4) * 8]);
            LDSM_X4_T(b[0], b[1], b[2], b[3], addr);
            #pragma unroll
            for (int m = 0; m < 2; m++) {
                MMA16816(acc[m][2 * jp],     a[m], b[0], b[1]);
                MMA16816(acc[m][2 * jp + 1], a[m], b[2], b[3]);
            }
        }
    }
}

// Layer-1 fused GEMM: hw = fp16(x@W0)  AND  g_part = fp32(x@Wl[0:128])
__global__ void __launch_bounds__(128) k_hmma_l1(
    const float* __restrict__ x,
    const float* __restrict__ W0,
    const float* __restrict__ Wl,
    __half2* __restrict__ out, int n)
{
    __shared__ __half sA[128][PADH];
    __shared__ __half sBw[64][PADH];
    __shared__ __half sBl[64][PADH];
    int t = threadIdx.x;
    int lane = t & 31, warp = t >> 5;
    int rowBase = blockIdx.x * 128;
    float accW[2][8][4] = {};
    float accL[2][8][4] = {};

    for (int i = 0; i < 2; i++) {
        load_A32g(sA, x, 128, i * 64, rowBase, n, t);
        load_Bg(sBw, W0, i * 64, t);
        load_Bg(sBl, Wl, i * 64, t);
        __syncthreads();
        hmma_tile_g(sA, sBw, warp, lane, accW);
        hmma_tile_g(sA, sBl, warp, lane, accL);
        __syncthreads();
    }

    int rw = rowBase + warp * 32;
    #pragma unroll
    for (int m = 0; m < 2; m++) {
        int r0 = rw + m * 16 + (lane >> 2);
        int r1 = r0 + 8;
        #pragma unroll
        for (int j = 0; j < 8; j++) {
            int col = 8 * j + 2 * (lane & 3);
            if (r0 < n) {
                out[(size_t)r0 * 32 + (col >> 1)] =
                    __floats2half2_rn(accW[m][j][0], accW[m][j][1]);
                *(float2*)&g_part[(size_t)r0 * 64 + col] =
                    make_float2(accL[m][j][0], accL[m][j][1]);
            }
            if (r1 < n) {
                out[(size_t)r1 * 32 + (col >> 1)] =
                    __floats2half2_rn(accW[m][j][2], accW[m][j][3]);
                *(float2*)&g_part[(size_t)r1 * 64 + col] =
                    make_float2(accL[m][j][2], accL[m][j][3]);
            }
        }
    }
}

// Layers 2,3 transform GEMM: out = fp16(A16 @ W), K=64
__global__ void __launch_bounds__(128) k_hmma_xform(
    const __half2* __restrict__ A16,
    const float* __restrict__ W,
    __half2* __restrict__ out, int n)
{
    __shared__ __half sA[128][PADH];
    __shared__ __half sB[64][PADH];
    int t = threadIdx.x;
    int lane = t & 31, warp = t >> 5;
    int rowBase = blockIdx.x * 128;
    float acc[2][8][4] = {};

    load_A16g(sA, A16, rowBase, n, t);
    load_Bg(sB, W, 0, t);
    __syncthreads();
    hmma_tile_g(sA, sB, warp, lane, acc);
    __syncthreads();

    int rw = rowBase + warp * 32;
    #pragma unroll
    for (int m = 0; m < 2; m++) {
        int r0 = rw + m * 16 + (lane >> 2);
        int r1 = r0 + 8;
        #pragma unroll
        for (int j = 0; j < 8; j++) {
            int col = 8 * j + 2 * (lane & 3);
            if (r0 < n)
                out[(size_t)r0 * 32 + (col >> 1)] =
                    __floats2half2_rn(acc[m][j][0], acc[m][j][1]);
            if (r1 < n)
                out[(size_t)r1 * 32 + (col >> 1)] =
                    __floats2half2_rn(acc[m][j][2], acc[m][j][3]);
        }
    }
}

// Final GEMM: out = partial + [h1|h2|h3] @ Wl[128:320] + bl   (K=192, fp16 A)
__global__ void __launch_bounds__(128) k_hmma_cat(
    const float* __restrict__ Wl,
    const float* __restrict__ bl,
    float* __restrict__ out, int n)
{
    __shared__ __half sA[128][PADH];
    __shared__ __half sB[64][PADH];
    int t = threadIdx.x;
    int lane = t & 31, warp = t >> 5;
    int rowBase = blockIdx.x * 128;
    float acc[2][8][4] = {};
    const float* Wl2 = Wl + 128 * 64;

    for (int i = 0; i < 3; i++) {
        const __half2* src = (i == 0) ? g_h1 : (i == 1) ? g_h2 : g_h3;
        load_A16g(sA, src, rowBase, n, t);
        load_Bg(sB, Wl2, i * 64, t);
        __syncthreads();
        hmma_tile_g(sA, sB, warp, lane, acc);
        __syncthreads();
    }

    int rw = rowBase + warp * 32;
    #pragma unroll
    for (int m = 0; m < 2; m++) {
        int r0 = rw + m * 16 + (lane >> 2);
        int r1 = r0 + 8;
        #pragma unroll
        for (int j = 0; j < 8; j++) {
            int col = 8 * j + 2 * (lane & 3);
            float b0 = bl[col], b1 = bl[col + 1];
            if (r0 < n) {
                float2 p = *(const float2*)&g_part[(size_t)r0 * 64 + col];
                *(float2*)&out[(size_t)r0 * 64 + col] =
                    make_float2(acc[m][j][0] + p.x + b0, acc[m][j][1] + p.y + b1);
            }
            if (r1 < n) {
                float2 p = *(const float2*)&g_part[(size_t)r1 * 64 + col];
                *(float2*)&out[(size_t)r1 * 64 + col] =
                    make_float2(acc[m][j][2] + p.x + b0, acc[m][j][3] + p.y + b1);
            }
        }
    }
}

// ===========================================================================
// Aggregation: warp per node, lane = one half2 (2 cols), unroll x8.
// cv stream loaded as uniform int4 (LDG.128) -- 4 issues per 8 edges instead
// of 8. Alignment prologue handles odd beg (g_cv is 8B-granular).
// ===========================================================================
__device__ __forceinline__ void gather_edge(
    const __half2* __restrict__ hw, int lane, int col, int vbits,
    float& a0, float& a1)
{
    float2 f = __half22float2(hw[(size_t)col * 32 + lane]);
    float v = __int_as_float(vbits);
    a0 = fmaf(v, f.x, a0);
    a1 = fmaf(v, f.y, a1);
}

__global__ void __launch_bounds__(256) k_gather(
    const __half2* __restrict__ hw,
    const float* __restrict__ bias,
    __half2* __restrict__ hout, int n)
{
    int g = blockIdx.x * blockDim.x + threadIdx.x;
    int node = g >> 5;
    int lane = g & 31;
    if (node >= n) return;
    int beg = g_rowptr[node];
    int end = g_rowptr[node + 1];
    float a0 = 0.f, a1 = 0.f;
    int e = beg;
    if ((e & 1) && e < end) {              // align to 16B for int4 cv loads
        int2 cv = __ldg(&g_cv[e]);
        gather_edge(hw, lane, cv.x, cv.y, a0, a1);
        e++;
    }
    for (; e + 7 < end; e += 8) {
        int4 q0 = __ldg((const int4*)&g_cv[e]);
        int4 q1 = __ldg((const int4*)&g_cv[e + 2]);
        int4 q2 = __ldg((const int4*)&g_cv[e + 4]);
        int4 q3 = __ldg((const int4*)&g_cv[e + 6]);
        float2 f[8];
        f[0] = __half22float2(hw[(size_t)q0.x * 32 + lane]);
        f[1] = __half22float2(hw[(size_t)q0.z * 32 + lane]);
        f[2] = __half22float2(hw[(size_t)q1.x * 32 + lane]);
        f[3] = __half22float2(hw[(size_t)q1.z * 32 + lane]);
        f[4] = __half22float2(hw[(size_t)q2.x * 32 + lane]);
        f[5] = __half22float2(hw[(size_t)q2.z * 32 + lane]);
        f[6] = __half22float2(hw[(size_t)q3.x * 32 + lane]);
        f[7] = __half22float2(hw[(size_t)q3.z * 32 + lane]);
        float v0 = __int_as_float(q0.y), v1 = __int_as_float(q0.w);
        float v2 = __int_as_float(q1.y), v3 = __int_as_float(q1.w);
        float v4 = __int_as_float(q2.y), v5 = __int_as_float(q2.w);
        float v6 = __int_as_float(q3.y), v7 = __int_as_float(q3.w);
        a0 = fmaf(v0, f[0].x, a0); a1 = fmaf(v0, f[0].y, a1);
        a0 = fmaf(v1, f[1].x, a0); a1 = fmaf(v1, f[1].y, a1);
        a0 = fmaf(v2, f[2].x, a0); a1 = fmaf(v2, f[2].y, a1);
        a0 = fmaf(v3, f[3].x, a0); a1 = fmaf(v3, f[3].y, a1);
        a0 = fmaf(v4, f[4].x, a0); a1 = fmaf(v4, f[4].y, a1);
        a0 = fmaf(v5, f[5].x, a0); a1 = fmaf(v5, f[5].y, a1);
        a0 = fmaf(v6, f[6].x, a0); a1 = fmaf(v6, f[6].y, a1);
        a0 = fmaf(v7, f[7].x, a0); a1 = fmaf(v7, f[7].y, a1);
    }
    for (; e < end; e++) {
        int2 cv = __ldg(&g_cv[e]);
        gather_edge(hw, lane, cv.x, cv.y, a0, a1);
    }
    float b0 = bias[2 * lane], b1 = bias[2 * lane + 1];
    hout[(size_t)node * 32 + lane] =
        __floats2half2_rn(fmaxf(a0 + b0, 0.f), fmaxf(a1 + b1, 0.f));
}

// ---------------------------------------------------------------------------
extern "C" void kernel_launch(void* const* d_in, const int* in_sizes, int n_in,
                              void* d_out, int out_size)
{
    const float* x  = (const float*)d_in[0];
    const int*   ei = (const int*)d_in[1];     // int32 edge_index [2, E]
    const float* W0 = (const float*)d_in[2];
    const float* b0 = (const float*)d_in[3];
    const float* W1 = (const float*)d_in[4];
    const float* b1 = (const float*)d_in[5];
    const float* W2 = (const float*)d_in[6];
    const float* b2 = (const float*)d_in[7];
    const float* Wl = (const float*)d_in[8];
    const float* bl = (const float*)d_in[9];
    float* out = (float*)d_out;

    int n = in_sizes[0] / 128;
    int e = in_sizes[1] / 2;
    int nb = (n + 1023) >> 10;

    __half2 *hw_ptr = nullptr, *h1_ptr = nullptr, *h2_ptr = nullptr, *h3_ptr = nullptr;
    cudaGetSymbolAddress((void**)&hw_ptr, g_hw);
    cudaGetSymbolAddress((void**)&h1_ptr, g_h1);
    cudaGetSymbolAddress((void**)&h2_ptr, g_h2);
    cudaGetSymbolAddress((void**)&h3_ptr, g_h3);

    int mma_blocks = (n + 127) / 128;
    int gather_blocks = (n * 32 + 255) / 256;

    // ---- fork: layer-1 GEMM on side stream, CSR build on main stream ----
    cudaStream_t s2;
    cudaStreamCreate(&s2);
    cudaEvent_t evA, evB;
    cudaEventCreateWithFlags(&evA, cudaEventDisableTiming);
    cudaEventCreateWithFlags(&evB, cudaEventDisableTiming);

    cudaEventRecord(evA, 0);
    cudaStreamWaitEvent(s2, evA, 0);
    k_hmma_l1<<<mma_blocks, 128, 0, s2>>>(x, W0, Wl, hw_ptr, n);
    cudaEventRecord(evB, s2);

    // ---- CSR build (main stream) ----
    if ((e & 3) == 0) {
        int cth = e / 4;
        k_count4<<<(cth + 255) / 256, 256>>>(ei, e);
    } else {
        k_count1<<<(e + 255) / 256, 256>>>(ei, e);
    }
    k_scan_local<<<nb, 1024>>>(n);
    k_scan_add<<<nb, 1024>>>(nb, n);
    k_fill<<<(e + n + 255) / 256, 256>>>(ei, e, n);

    // join: gather needs both CSR and hw
    cudaStreamWaitEvent(0, evB, 0);

    // ---- layer 1 aggregate ----
    k_gather<<<gather_blocks, 256>>>(hw_ptr, b0, h1_ptr, n);
    // ---- layer 2 ----
    k_hmma_xform<<<mma_blocks, 128>>>(h1_ptr, W1, hw_ptr, n);
    k_gather<<<gather_blocks, 256>>>(hw_ptr, b1, h2_ptr, n);
    // ---- layer 3 ----
    k_hmma_xform<<<mma_blocks, 128>>>(h2_ptr, W2, hw_ptr, n);
    k_gather<<<gather_blocks, 256>>>(hw_ptr, b2, h3_ptr, n);
    // ---- JK concat + linear (K=192 fp16 + partial) ----
    k_hmma_cat<<<mma_blocks, 128>>>(Wl, bl, out, n);

    cudaEventDestroy(evA);
    cudaEventDestroy(evB);
    cudaStreamDestroy(s2);
}

// round 13
// speedup vs baseline: 1.2321x; 1.0864x over previous
#include <cuda_runtime.h>
#include <cuda_fp16.h>
#include <cstdint>

// ---------------------------------------------------------------------------
// GCN_JK_Concat: 3x GCNConv(sym-norm, self-loops) + JK concat + Linear
// N=100000, E=1600000, F_IN=128, H=64, F_OUT=64
// R13: symmetric norm factored out of the edge stream:
//   sum_e dis[s]*dis[d]*f[s] = dis[d] * sum_e (dis[s]*f[s])
// dis[s] folded into transform-GEMM epilogue, dis[d] into gather epilogue.
// CSR stores ONLY col (4B/edge): fill has no random dis reads and half the
// scatter bytes; gather cols arrive as int4 (2 LDG.128 per 8 edges) and the
// inner op is a pure add. Otherwise identical to R12 (HMMA GEMMs, fused
// scan_add, stream-forked layer-1 GEMM, x@Wl partial fusion).
// ---------------------------------------------------------------------------

#define NMAX   100000
#define EMAX   1600000
#define NNZMAX (EMAX + NMAX)
#define NBSCAN 128

__device__ int     g_deg[NMAX];               // starts 0; reset by scan
__device__ float   g_dis[NMAX];
__device__ int     g_rowptr[NMAX + 1];
__device__ int     g_cursor[NMAX];
__device__ int     g_bsum[NBSCAN];
__device__ int     g_col[NNZMAX];             // col only (norm factored out)
__device__ __half2 g_hw[(size_t)NMAX * 32];   // dis-scaled fp16 messages
__device__ __half2 g_h1[(size_t)NMAX * 32];
__device__ __half2 g_h2[(size_t)NMAX * 32];
__device__ __half2 g_h3[(size_t)NMAX * 32];
__device__ float   g_part[(size_t)NMAX * 64]; // x @ Wl[0:128] partial (fp32)

// ===========================================================================
// CSR build
// ===========================================================================
__global__ void k_count4(const int* __restrict__ ei, int e) {
    int i = blockIdx.x * blockDim.x + threadIdx.x;
    int base = 4 * i;
    if (base + 3 < e) {
        int4 d = *(const int4*)&ei[(size_t)e + base];
        atomicAdd(&g_deg[d.x], 1);
        atomicAdd(&g_deg[d.y], 1);
        atomicAdd(&g_deg[d.z], 1);
        atomicAdd(&g_deg[d.w], 1);
    } else {
        for (int j = base; j < e; j++)
            atomicAdd(&g_deg[ei[(size_t)e + j]], 1);
    }
}

__global__ void k_count1(const int* __restrict__ ei, int e) {
    int i = blockIdx.x * blockDim.x + threadIdx.x;
    if (i < e) atomicAdd(&g_deg[ei[(size_t)e + i]], 1);
}

__global__ void __launch_bounds__(1024) k_scan_local(int n) {
    __shared__ int warpsum[32];
    int t = threadIdx.x;
    int lane = t & 31;
    int w = t >> 5;
    int i = blockIdx.x * 1024 + t;
    int v = 0;
    if (i < n) {
        v = g_deg[i] + 1;        // +1 = self-loop
        g_deg[i] = 0;            // reset for next graph replay
    }
    int s = v;
    #pragma unroll
    for (int o = 1; o < 32; o <<= 1) {
        int x = __shfl_up_sync(0xffffffffu, s, o);
        if (lane >= o) s += x;
    }
    if (lane == 31) warpsum[w] = s;
    __syncthreads();
    if (w == 0) {
        int v2 = warpsum[lane];
        #pragma unroll
        for (int o = 1; o < 32; o <<= 1) {
            int x = __shfl_up_sync(0xffffffffu, v2, o);
            if (lane >= o) v2 += x;
        }
        warpsum[lane] = v2;
    }
    __syncthreads();
    int prefix = (w == 0) ? 0 : warpsum[w - 1];
    int incl = prefix + s;
    if (i < n) {
        g_rowptr[i] = incl - v;
        g_dis[i] = rsqrtf((float)v);
    }
    if (t == 1023) g_bsum[blockIdx.x] = incl;
}

// Fused: per-block offset reduction + add pass
__global__ void __launch_bounds__(1024) k_scan_add(int nb, int n) {
    __shared__ int s_off;
    int t = threadIdx.x;
    int bid = blockIdx.x;
    if (t < 32) {
        int acc = 0;
        for (int j = t; j < nb; j += 32)
            if (j < bid) acc += g_bsum[j];
        #pragma unroll
        for (int o = 16; o; o >>= 1) acc += __shfl_down_sync(0xffffffffu, acc, o);
        if (t == 0) s_off = acc;
    }
    __syncthreads();
    int off = s_off;
    int i = bid * 1024 + t;
    if (i < n) {
        int rp = g_rowptr[i] + off;
        g_rowptr[i] = rp;
        g_cursor[i] = rp;
    }
    if (bid == gridDim.x - 1 && t < 32) {
        int acc2 = 0;
        for (int j = t; j < nb; j += 32) acc2 += g_bsum[j];
        #pragma unroll
        for (int o = 16; o; o >>= 1) acc2 += __shfl_down_sync(0xffffffffu, acc2, o);
        if (t == 0) g_rowptr[n] = acc2;
    }
}

// fill: scatter ONLY col (no dis reads, 4B stores)
__global__ void k_fill(const int* __restrict__ ei, int e, int n) {
    int i = blockIdx.x * blockDim.x + threadIdx.x;
    int s, d;
    if (i < e) {
        s = ei[i];
        d = ei[(size_t)e + i];
    } else if (i < e + n) {
        s = d = i - e;                  // self-loop
    } else {
        return;
    }
    int pos = atomicAdd(&g_cursor[d], 1);
    g_col[pos] = s;
}

// ===========================================================================
// HMMA GEMM machinery
// ===========================================================================
#define PADH 72

__device__ __forceinline__ uint32_t smem_u32(const void* p) {
    return (uint32_t)__cvta_generic_to_shared(p);
}

#define LDSM_X4(r0, r1, r2, r3, addr) \
    asm volatile("ldmatrix.sync.aligned.m8n8.x4.shared.b16 {%0,%1,%2,%3}, [%4];" \
        : "=r"(r0), "=r"(r1), "=r"(r2), "=r"(r3) : "r"(addr))

#define LDSM_X4_T(r0, r1, r2, r3, addr) \
    asm volatile("ldmatrix.sync.aligned.m8n8.x4.trans.shared.b16 {%0,%1,%2,%3}, [%4];" \
        : "=r"(r0), "=r"(r1), "=r"(r2), "=r"(r3) : "r"(addr))

#define MMA16816(d, a, b0, b1) \
    asm volatile("mma.sync.aligned.m16n8k16.row.col.f32.f16.f16.f32 " \
        "{%0,%1,%2,%3}, {%4,%5,%6,%7}, {%8,%9}, {%0,%1,%2,%3};" \
        : "+f"((d)[0]), "+f"((d)[1]), "+f"((d)[2]), "+f"((d)[3]) \
        : "r"((a)[0]), "r"((a)[1]), "r"((a)[2]), "r"((a)[3]), "r"(b0), "r"(b1))

typedef __half ARow[PADH];

__device__ __forceinline__ void load_A32g(
    ARow* sA, const float* __restrict__ A, int K, int kk,
    int rowBase, int n, int t)
{
    for (int idx = t; idx < 4096; idx += 128) {
        int row = idx >> 5, kp = idx & 31;
        int gr = rowBase + row;
        float2 f = make_float2(0.f, 0.f);
        if (gr < n) f = *(const float2*)&A[(size_t)gr * K + kk + 2 * kp];
        *(__half2*)&sA[row][2 * kp] = __float22half2_rn(f);
    }
}

__device__ __forceinline__ void load_A16g(
    ARow* sA, const __half2* __restrict__ H, int rowBase, int n, int t)
{
    for (int idx = t; idx < 1024; idx += 128) {
        int row = idx >> 3, q = idx & 7;
        int gr = rowBase + row;
        uint4 v = make_uint4(0u, 0u, 0u, 0u);
        if (gr < n) v = *(const uint4*)&H[(size_t)gr * 32 + 4 * q];
        *(uint4*)&sA[row][8 * q] = v;
    }
}

__device__ __forceinline__ void load_Bg(
    ARow* sB, const float* __restrict__ W, int kk, int t)
{
    for (int idx = t; idx < 2048; idx += 128) {
        int k = idx >> 5, np = idx & 31;
        float2 f = *(const float2*)&W[(size_t)(kk + k) * 64 + 2 * np];
        *(__half2*)&sB[k][2 * np] = __float22half2_rn(f);
    }
}

__device__ __forceinline__ void hmma_tile_g(
    ARow* sA, ARow* sB, int warp, int lane, float acc[2][8][4])
{
    #pragma unroll
    for (int kc = 0; kc < 4; kc++) {
        int k0 = kc * 16;
        uint32_t a[2][4];
        #pragma unroll
        for (int m = 0; m < 2; m++) {
            uint32_t addr = smem_u32(
                &sA[warp * 32 + m * 16 + (lane & 15)][k0 + (lane >> 4) * 8]);
            LDSM_X4(a[m][0], a[m][1], a[m][2], a[m][3], addr);
        }
        #pragma unroll
        for (int jp = 0; jp < 4; jp++) {
            uint32_t b[4];
            uint32_t addr = smem_u32(
                &sB[k0 + (lane & 15)][jp * 16 + (lane >> 4) * 8]);
            LDSM_X4_T(b[0], b[1], b[2], b[3], addr);
            #pragma unroll
            for (int m = 0; m < 2; m++) {
                MMA16816(acc[m][2 * jp],     a[m], b[0], b[1]);
                MMA16816(acc[m][2 * jp + 1], a[m], b[2], b[3]);
            }
        }
    }
}

// Layer-1 fused GEMM: hw = fp16(dis .* (x@W0))  AND  g_part = fp32(x@Wl[0:128])
__global__ void __launch_bounds__(128) k_hmma_l1(
    const float* __restrict__ x,
    const float* __restrict__ W0,
    const float* __restrict__ Wl,
    __half2* __restrict__ out, int n)
{
    __shared__ __half sA[128][PADH];
    __shared__ __half sBw[64][PADH];
    __shared__ __half sBl[64][PADH];
    int t = threadIdx.x;
    int lane = t & 31, warp = t >> 5;
    int rowBase = blockIdx.x * 128;
    float accW[2][8][4] = {};
    float accL[2][8][4] = {};

    for (int i = 0; i < 2; i++) {
        load_A32g(sA, x, 128, i * 64, rowBase, n, t);
        load_Bg(sBw, W0, i * 64, t);
        load_Bg(sBl, Wl, i * 64, t);
        __syncthreads();
        hmma_tile_g(sA, sBw, warp, lane, accW);
        hmma_tile_g(sA, sBl, warp, lane, accL);
        __syncthreads();
    }

    int rw = rowBase + warp * 32;
    #pragma unroll
    for (int m = 0; m < 2; m++) {
        int r0 = rw + m * 16 + (lane >> 2);
        int r1 = r0 + 8;
        float d0 = (r0 < n) ? g_dis[r0] : 0.f;
        float d1 = (r1 < n) ? g_dis[r1] : 0.f;
        #pragma unroll
        for (int j = 0; j < 8; j++) {
            int col = 8 * j + 2 * (lane & 3);
            if (r0 < n) {
                out[(size_t)r0 * 32 + (col >> 1)] =
                    __floats2half2_rn(accW[m][j][0] * d0, accW[m][j][1] * d0);
                *(float2*)&g_part[(size_t)r0 * 64 + col] =
                    make_float2(accL[m][j][0], accL[m][j][1]);
            }
            if (r1 < n) {
                out[(size_t)r1 * 32 + (col >> 1)] =
                    __floats2half2_rn(accW[m][j][2] * d1, accW[m][j][3] * d1);
                *(float2*)&g_part[(size_t)r1 * 64 + col] =
                    make_float2(accL[m][j][2], accL[m][j][3]);
            }
        }
    }
}

// Layers 2,3 transform GEMM: out = fp16(dis .* (A16 @ W)), K=64
__global__ void __launch_bounds__(128) k_hmma_xform(
    const __half2* __restrict__ A16,
    const float* __restrict__ W,
    __half2* __restrict__ out, int n)
{
    __shared__ __half sA[128][PADH];
    __shared__ __half sB[64][PADH];
    int t = threadIdx.x;
    int lane = t & 31, warp = t >> 5;
    int rowBase = blockIdx.x * 128;
    float acc[2][8][4] = {};

    load_A16g(sA, A16, rowBase, n, t);
    load_Bg(sB, W, 0, t);
    __syncthreads();
    hmma_tile_g(sA, sB, warp, lane, acc);
    __syncthreads();

    int rw = rowBase + warp * 32;
    #pragma unroll
    for (int m = 0; m < 2; m++) {
        int r0 = rw + m * 16 + (lane >> 2);
        int r1 = r0 + 8;
        float d0 = (r0 < n) ? g_dis[r0] : 0.f;
        float d1 = (r1 < n) ? g_dis[r1] : 0.f;
        #pragma unroll
        for (int j = 0; j < 8; j++) {
            int col = 8 * j + 2 * (lane & 3);
            if (r0 < n)
                out[(size_t)r0 * 32 + (col >> 1)] =
                    __floats2half2_rn(acc[m][j][0] * d0, acc[m][j][1] * d0);
            if (r1 < n)
                out[(size_t)r1 * 32 + (col >> 1)] =
                    __floats2half2_rn(acc[m][j][2] * d1, acc[m][j][3] * d1);
        }
    }
}

// Final GEMM: out = partial + [h1|h2|h3] @ Wl[128:320] + bl   (K=192, fp16 A)
__global__ void __launch_bounds__(128) k_hmma_cat(
    const float* __restrict__ Wl,
    const float* __restrict__ bl,
    float* __restrict__ out, int n)
{
    __shared__ __half sA[128][PADH];
    __shared__ __half sB[64][PADH];
    int t = threadIdx.x;
    int lane = t & 31, warp = t >> 5;
    int rowBase = blockIdx.x * 128;
    float acc[2][8][4] = {};
    const float* Wl2 = Wl + 128 * 64;

    for (int i = 0; i < 3; i++) {
        const __half2* src = (i == 0) ? g_h1 : (i == 1) ? g_h2 : g_h3;
        load_A16g(sA, src, rowBase, n, t);
        load_Bg(sB, Wl2, i * 64, t);
        __syncthreads();
        hmma_tile_g(sA, sB, warp, lane, acc);
        __syncthreads();
    }

    int rw = rowBase + warp * 32;
    #pragma unroll
    for (int m = 0; m < 2; m++) {
        int r0 = rw + m * 16 + (lane >> 2);
        int r1 = r0 + 8;
        #pragma unroll
        for (int j = 0; j < 8; j++) {
            int col = 8 * j + 2 * (lane & 3);
            float b0 = bl[col], b1 = bl[col + 1];
            if (r0 < n) {
                float2 p = *(const float2*)&g_part[(size_t)r0 * 64 + col];
                *(float2*)&out[(size_t)r0 * 64 + col] =
                    make_float2(acc[m][j][0] + p.x + b0, acc[m][j][1] + p.y + b1);
            }
            if (r1 < n) {
                float2 p = *(const float2*)&g_part[(size_t)r1 * 64 + col];
                *(float2*)&out[(size_t)r1 * 64 + col] =
                    make_float2(acc[m][j][2] + p.x + b0, acc[m][j][3] + p.y + b1);
            }
        }
    }
}

// ===========================================================================
// Aggregation: warp per node, lane = one half2 (2 cols), unroll x8.
// Cols arrive as int4 (2 LDG.128 per 8 edges). Inner op is a pure ADD;
// node-level dis[d] applied in the epilogue.
// ===========================================================================
__global__ void __launch_bounds__(256) k_gather(
    const __half2* __restrict__ hw,
    const float* __restrict__ bias,
    __half2* __restrict__ hout, int n)
{
    int g = blockIdx.x * blockDim.x + threadIdx.x;
    int node = g >> 5;
    int lane = g & 31;
    if (node >= n) return;
    int beg = g_rowptr[node];
    int end = g_rowptr[node + 1];
    float disd = g_dis[node];
    float a0 = 0.f, a1 = 0.f;
    int e = beg;
    // align to 16B (4-int) boundary for int4 col loads
    while ((e & 3) && e < end) {
        int c = __ldg(&g_col[e]);
        float2 f = __half22float2(hw[(size_t)c * 32 + lane]);
        a0 += f.x; a1 += f.y;
        e++;
    }
    for (; e + 7 < end; e += 8) {
        int4 c0 = __ldg((const int4*)&g_col[e]);
        int4 c1 = __ldg((const int4*)&g_col[e + 4]);
        float2 f0 = __half22float2(hw[(size_t)c0.x * 32 + lane]);
        float2 f1 = __half22float2(hw[(size_t)c0.y * 32 + lane]);
        float2 f2 = __half22float2(hw[(size_t)c0.z * 32 + lane]);
        float2 f3 = __half22float2(hw[(size_t)c0.w * 32 + lane]);
        float2 f4 = __half22float2(hw[(size_t)c1.x * 32 + lane]);
        float2 f5 = __half22float2(hw[(size_t)c1.y * 32 + lane]);
        float2 f6 = __half22float2(hw[(size_t)c1.z * 32 + lane]);
        float2 f7 = __half22float2(hw[(size_t)c1.w * 32 + lane]);
        a0 += f0.x + f1.x + f2.x + f3.x;
        a1 += f0.y + f1.y + f2.y + f3.y;
        a0 += f4.x + f5.x + f6.x + f7.x;
        a1 += f4.y + f5.y + f6.y + f7.y;
    }
    for (; e < end; e++) {
        int c = __ldg(&g_col[e]);
        float2 f = __half22float2(hw[(size_t)c * 32 + lane]);
        a0 += f.x; a1 += f.y;
    }
    float b0 = bias[2 * lane], b1 = bias[2 * lane + 1];
    hout[(size_t)node * 32 + lane] =
        __floats2half2_rn(fmaxf(fmaf(disd, a0, b0), 0.f),
                          fmaxf(fmaf(disd, a1, b1), 0.f));
}

// ---------------------------------------------------------------------------
extern "C" void kernel_launch(void* const* d_in, const int* in_sizes, int n_in,
                              void* d_out, int out_size)
{
    const float* x  = (const float*)d_in[0];
    const int*   ei = (const int*)d_in[1];     // int32 edge_index [2, E]
    const float* W0 = (const float*)d_in[2];
    const float* b0 = (const float*)d_in[3];
    const float* W1 = (const float*)d_in[4];
    const float* b1 = (const float*)d_in[5];
    const float* W2 = (const float*)d_in[6];
    const float* b2 = (const float*)d_in[7];
    const float* Wl = (const float*)d_in[8];
    const float* bl = (const float*)d_in[9];
    float* out = (float*)d_out;

    int n = in_sizes[0] / 128;
    int e = in_sizes[1] / 2;
    int nb = (n + 1023) >> 10;

    __half2 *hw_ptr = nullptr, *h1_ptr = nullptr, *h2_ptr = nullptr, *h3_ptr = nullptr;
    cudaGetSymbolAddress((void**)&hw_ptr, g_hw);
    cudaGetSymbolAddress((void**)&h1_ptr, g_h1);
    cudaGetSymbolAddress((void**)&h2_ptr, g_h2);
    cudaGetSymbolAddress((void**)&h3_ptr, g_h3);

    int mma_blocks = (n + 127) / 128;
    int gather_blocks = (n * 32 + 255) / 256;

    // ---- fork: CSR count/scan on main stream; layer-1 GEMM needs dis (from
    // scan) for its epilogue, so it launches on s2 after scan completes,
    // overlapping with k_fill.
    cudaStream_t s2;
    cudaStreamCreate(&s2);
    cudaEvent_t evScan, evL1;
    cudaEventCreateWithFlags(&evScan, cudaEventDisableTiming);
    cudaEventCreateWithFlags(&evL1, cudaEventDisableTiming);

    // ---- CSR build (main stream) ----
    if ((e & 3) == 0) {
        int cth = e / 4;
        k_count4<<<(cth + 255) / 256, 256>>>(ei, e);
    } else {
        k_count1<<<(e + 255) / 256, 256>>>(ei, e);
    }
    k_scan_local<<<nb, 1024>>>(n);
    k_scan_add<<<nb, 1024>>>(nb, n);
    cudaEventRecord(evScan, 0);

    // layer-1 GEMM on side stream (needs dis; overlaps with k_fill)
    cudaStreamWaitEvent(s2, evScan, 0);
    k_hmma_l1<<<mma_blocks, 128, 0, s2>>>(x, W0, Wl, hw_ptr, n);
    cudaEventRecord(evL1, s2);

    k_fill<<<(e + n + 255) / 256, 256>>>(ei, e, n);

    // join: gather needs both CSR fill and hw
    cudaStreamWaitEvent(0, evL1, 0);

    // ---- layer 1 aggregate ----
    k_gather<<<gather_blocks, 256>>>(hw_ptr, b0, h1_ptr, n);
    // ---- layer 2 ----
    k_hmma_xform<<<mma_blocks, 128>>>(h1_ptr, W1, hw_ptr, n);
    k_gather<<<gather_blocks, 256>>>(hw_ptr, b1, h2_ptr, n);
    // ---- layer 3 ----
    k_hmma_xform<<<mma_blocks, 128>>>(h2_ptr, W2, hw_ptr, n);
    k_gather<<<gather_blocks, 256>>>(hw_ptr, b2, h3_ptr, n);
    // ---- JK concat + linear (K=192 fp16 + partial) ----
    k_hmma_cat<<<mma_blocks, 128>>>(Wl, bl, out, n);

    cudaEventDestroy(evScan);
    cudaEventDestroy(evL1);
    cudaStreamDestroy(s2);
}